// round 9
// baseline (speedup 1.0000x reference)
#include <cuda_runtime.h>

// ============================================================================
// TorusConv3D via FFT diagonalization (round 9).
// Round-9: PDL (programmatic dependent launch) to overlap the 3-stage chain's
// launch/drain gaps; ifft widened to 512 threads. Per-stage math/shapes kept
// from their best measured rounds (packed f32x2 butterflies, Hermitian
// pointwise with packed real-pair spectra).
// ============================================================================

typedef unsigned long long ull;

// Packed spectra: g_Xp[k*2048 + b*32 + j], g_Wp[k*2048 + f*32 + j],
//                 g_Z [k*2048 + b*32 + fp]
__device__ ull g_Xp[512 * 2048];
__device__ ull g_Wp[512 * 2048];
__device__ ull g_Z[512 * 2048];

// ---------------------------------------------------------------------------
// PDL intrinsics (no-ops when the launch lacks the PDL attribute).
// ---------------------------------------------------------------------------
__device__ __forceinline__ void pdl_launch_dependents() {
    asm volatile("griddepcontrol.launch_dependents;");
}
__device__ __forceinline__ void pdl_wait() {
    asm volatile("griddepcontrol.wait;" ::: "memory");
}

// ---------------------------------------------------------------------------
// Packed f32x2 primitives. A complex value is (re, im) = (lo, hi) of an ull.
// ---------------------------------------------------------------------------
__device__ __forceinline__ ull pk(float lo, float hi) {
    ull r;
    asm("mov.b64 %0, {%1, %2};" : "=l"(r) : "f"(lo), "f"(hi));
    return r;
}
__device__ __forceinline__ void upk(ull v, float& lo, float& hi) {
    asm("mov.b64 {%0, %1}, %2;" : "=f"(lo), "=f"(hi) : "l"(v));
}
__device__ __forceinline__ ull add2(ull a, ull b) {
    ull d;
    asm("add.rn.f32x2 %0, %1, %2;" : "=l"(d) : "l"(a), "l"(b));
    return d;
}
__device__ __forceinline__ ull mul2(ull a, ull b) {
    ull d;
    asm("mul.rn.f32x2 %0, %1, %2;" : "=l"(d) : "l"(a), "l"(b));
    return d;
}
__device__ __forceinline__ ull fma2(ull a, ull b, ull c) {
    ull d;
    asm("fma.rn.f32x2 %0, %1, %2, %3;" : "=l"(d) : "l"(a), "l"(b), "l"(c));
    return d;
}
__device__ __forceinline__ ull sub2(ull a, ull b) {
    return fma2(b, 0xBF800000BF800000ULL, a);  // a + (-1)*b
}
__device__ __forceinline__ float negf(float x) {
    return __uint_as_float(__float_as_uint(x) ^ 0x80000000u);
}
template <int INV>
__device__ __forceinline__ ull mi(ull a) {  // *(-i) fwd, *(+i) inv
    float x, y;
    upk(a, x, y);
    return INV ? pk(negf(y), x) : pk(y, negf(x));
}

#define R2R2 0x3F3504F33F3504F3ULL  // (sqrt(0.5), sqrt(0.5))

// Radix-2 DIT 8-point FFT on packed complex. Forward = e^{-2pi i nk/8}.
template <int INV>
__device__ __forceinline__ void fft8p(ull* v) {
    ull t0 = add2(v[0], v[4]), t1 = sub2(v[0], v[4]);
    ull t2 = add2(v[2], v[6]), t3 = sub2(v[2], v[6]);
    ull t4 = add2(v[1], v[5]), t5 = sub2(v[1], v[5]);
    ull t6 = add2(v[3], v[7]), t7 = sub2(v[3], v[7]);
    ull a0 = add2(t0, t2), a1 = sub2(t0, t2);
    ull m3 = mi<INV>(t3);
    ull a2 = add2(t1, m3), a3 = sub2(t1, m3);
    ull b0 = add2(t4, t6), b1 = sub2(t4, t6);
    ull m7 = mi<INV>(t7);
    ull b2 = add2(t5, m7), b3 = sub2(t5, m7);
    ull mb1 = mi<INV>(b1);
    ull w1v = mul2(add2(b2, mi<INV>(b2)), R2R2);
    ull w3v = mi<INV>(mul2(add2(b3, mi<INV>(b3)), R2R2));
    v[0] = add2(a0, b0); v[4] = sub2(a0, b0);
    v[2] = add2(a1, mb1); v[6] = sub2(a1, mb1);
    v[1] = add2(a2, w1v); v[5] = sub2(a2, w1v);
    v[3] = add2(a3, w3v); v[7] = sub2(a3, w3v);
}

// ---------------------------------------------------------------------------
// Forward packed FFT, 16-column tiles, 512 threads.
// Blocks [0,128) -> inputs->Xp, [128,256) -> kernel->Wp.
// ---------------------------------------------------------------------------
__global__ void __launch_bounds__(512)
fft3d_fwd_packed(const float* __restrict__ inA, const float* __restrict__ inB,
                 ull* __restrict__ outA, ull* __restrict__ outB) {
    pdl_launch_dependents();  // let pointwise CTAs launch + run prologue
    extern __shared__ ull V[];
    int blk = blockIdx.x;
    const float* in;
    ull* out;
    long rowStride, sStride;
    if (blk < 128) { in = inA; out = outA; rowStride = 32768; sStride = 64; }
    else           { blk -= 128; in = inB; out = outB; rowStride = 64; sStride = 4096; }
    const int row = blk >> 1, j0 = (blk & 1) * 16;
    const int tid = threadIdx.x;
    const int c = tid & 15, pp = tid >> 4;

    const float* base = in + (long)row * rowStride + 2 * (j0 + c);
    ull buf[8];

    // Phase 1: z-axis fused with packed global load. t = (x,y), s = 8t + z.
#pragma unroll
    for (int m = 0; m < 2; ++m) {
        const int t = pp + 32 * m;
#pragma unroll
        for (int z = 0; z < 8; ++z)
            buf[z] = *(const ull*)(base + (long)(8 * t + z) * sStride);
        fft8p<0>(buf);
#pragma unroll
        for (int z = 0; z < 8; ++z) V[(8 * t + z) * 16 + c] = buf[z];
    }
    __syncthreads();

    // Phase 2: y-axis through smem. t = (x,z). stride 128.
#pragma unroll
    for (int m = 0; m < 2; ++m) {
        const int t = pp + 32 * m;
        const int b0 = ((t >> 3) * 64 + (t & 7)) * 16 + c;
#pragma unroll
        for (int y = 0; y < 8; ++y) buf[y] = V[b0 + y * 128];
        fft8p<0>(buf);
#pragma unroll
        for (int y = 0; y < 8; ++y) V[b0 + y * 128] = buf[y];
    }
    __syncthreads();

    // Phase 3: x-axis fused with global store. t = (ky,kz). stride 1024.
    ull* og = out + row * 32 + j0 + c;
#pragma unroll
    for (int m = 0; m < 2; ++m) {
        const int t = pp + 32 * m;
#pragma unroll
        for (int x = 0; x < 8; ++x) buf[x] = V[t * 16 + c + x * 1024];
        fft8p<0>(buf);
#pragma unroll
        for (int x = 0; x < 8; ++x) og[(long)(x * 64 + t) * 2048] = buf[x];
    }
}

// ---------------------------------------------------------------------------
// Hermitian pointwise complex GEMM (260 blocks, 256 threads, 4x4 tiles).
// PDL: waits for fwd only right before reading the spectra.
// ---------------------------------------------------------------------------
__global__ void __launch_bounds__(256)
pointwise_kernel(const float2* __restrict__ Xp, const float2* __restrict__ Wp,
                 float2* __restrict__ Zh) {
    pdl_launch_dependents();  // let ifft CTAs launch + run prologue
    const int rank = blockIdx.x;
    int kx, ky, kz;
    if (rank < 192) {
        kx = 1 + rank / 64; const int r = rank & 63; ky = r >> 3; kz = r & 7;
    } else if (rank < 240) {
        const int r = rank - 192; kx = (r / 24) * 4;
        const int r2 = r % 24; ky = 1 + r2 / 8; kz = r2 & 7;
    } else {
        const int r = rank - 240; kx = (r / 10) * 4;
        const int r2 = r % 10; ky = (r2 / 5) * 4; kz = r2 % 5;
    }
    const int k = (kx << 6) | (ky << 3) | kz;
    const int neg = (((8 - kx) & 7) << 6) | (((8 - ky) & 7) << 3) | ((8 - kz) & 7);

    extern __shared__ float2 sm[];
    float2* As = sm;            // [c][b], stride 65
    float2* Bs = sm + 64 * 65;  // [c][f], stride 65
    const int tid = threadIdx.x;

    const float2* xk = Xp + (long)k * 2048;
    const float2* xn = Xp + (long)neg * 2048;
    const float2* wk = Wp + (long)k * 2048;
    const float2* wn = Wp + (long)neg * 2048;

    pdl_wait();  // fwd FFT results must be visible beyond this point

    for (int i = tid; i < 2048; i += 256) {
        const int j = i & 31, rowi = i >> 5;
        const int c0 = 2 * j, c1 = 2 * j + 1;
        {
            const float2 Pk = xk[i], Pn = xn[i];
            As[c0 * 65 + rowi] = make_float2(0.5f * (Pk.x + Pn.x), 0.5f * (Pk.y - Pn.y));
            As[c1 * 65 + rowi] = make_float2(0.5f * (Pk.y + Pn.y), 0.5f * (Pn.x - Pk.x));
        }
        {
            const float2 Pk = wk[i], Pn = wn[i];
            Bs[c0 * 65 + rowi] = make_float2(0.5f * (Pk.x + Pn.x), 0.5f * (Pk.y - Pn.y));
            Bs[c1 * 65 + rowi] = make_float2(0.5f * (Pk.y + Pn.y), 0.5f * (Pn.x - Pk.x));
        }
    }
    __syncthreads();

    const int ft = tid & 15;
    const int bt = tid >> 4;
    ull acc[4][4];
#pragma unroll
    for (int i = 0; i < 4; ++i)
#pragma unroll
        for (int j = 0; j < 4; ++j) acc[i][j] = 0ULL;

    ull axax[4], nay[4], bxy[4], byx[4];
#pragma unroll 2
    for (int cc = 0; cc < 64; ++cc) {
#pragma unroll
        for (int i = 0; i < 4; ++i) {
            const float2 t = As[cc * 65 + bt + 16 * i];
            axax[i] = pk(t.x, t.x);
            nay[i] = pk(negf(t.y), t.y);
        }
#pragma unroll
        for (int j = 0; j < 4; ++j) {
            const float2 t = Bs[cc * 65 + ft + 16 * j];
            bxy[j] = pk(t.x, t.y);
            byx[j] = pk(t.y, t.x);
        }
#pragma unroll
        for (int i = 0; i < 4; ++i)
#pragma unroll
            for (int j = 0; j < 4; ++j) {
                acc[i][j] = fma2(axax[i], bxy[j], acc[i][j]);
                acc[i][j] = fma2(nay[i], byx[j], acc[i][j]);
            }
    }

    // Drain: pack f-pairs Z = Y_{2fp} + i*Y_{2fp+1}. Even-ft lanes own fp.
    float2* zk = Zh + (long)k * 2048;
    float2* zn = Zh + (long)neg * 2048;
    const bool self = (k == neg);
    const bool even = (ft & 1) == 0;
    const int fp0 = ft >> 1;
#pragma unroll
    for (int i = 0; i < 4; ++i)
#pragma unroll
        for (int j = 0; j < 4; ++j) {
            const ull part = __shfl_xor_sync(0xffffffffu, acc[i][j], 1);
            if (even) {
                float y0x, y0y, y1x, y1y;
                upk(acc[i][j], y0x, y0y);
                upk(part, y1x, y1y);
                const int idx = (bt + 16 * i) * 32 + fp0 + 8 * j;
                zk[idx] = make_float2(y0x - y1y, y0y + y1x);
                if (!self) zn[idx] = make_float2(y0x + y1y, y1x - y0y);
            }
        }
}

// ---------------------------------------------------------------------------
// Inverse packed FFT + bias, 16-column tiles, 512 threads, grid 128.
// PDL: waits for pointwise right before reading Z.
// ---------------------------------------------------------------------------
__global__ void __launch_bounds__(512)
ifft3d_packed(const ull* __restrict__ Zh, const float* __restrict__ bias,
              float* __restrict__ out) {
    extern __shared__ ull V[];
    const int b = blockIdx.x >> 1, fp0 = (blockIdx.x & 1) * 16;
    const int tid = threadIdx.x;
    const int c = tid & 15, pp = tid >> 4;
    const float2 bv = ((const float2*)bias)[fp0 + c];  // harness input: safe pre-wait

    const ull* yg = Zh + b * 32 + fp0 + c;
    ull buf[8];

    pdl_wait();  // pointwise results must be visible beyond this point

    // Phase 1: z-axis fused with load.
#pragma unroll
    for (int m = 0; m < 2; ++m) {
        const int t = pp + 32 * m;
#pragma unroll
        for (int z = 0; z < 8; ++z) buf[z] = yg[(long)(8 * t + z) * 2048];
        fft8p<1>(buf);
#pragma unroll
        for (int z = 0; z < 8; ++z) V[(8 * t + z) * 16 + c] = buf[z];
    }
    __syncthreads();

    // Phase 2: y-axis.
#pragma unroll
    for (int m = 0; m < 2; ++m) {
        const int t = pp + 32 * m;
        const int b0 = ((t >> 3) * 64 + (t & 7)) * 16 + c;
#pragma unroll
        for (int y = 0; y < 8; ++y) buf[y] = V[b0 + y * 128];
        fft8p<1>(buf);
#pragma unroll
        for (int y = 0; y < 8; ++y) V[b0 + y * 128] = buf[y];
    }
    __syncthreads();

    // Phase 3: x-axis fused with store (re -> 2fp, im -> 2fp+1, +bias).
    float2* og = (float2*)out + (long)b * 512 * 32 + fp0 + c;
#pragma unroll
    for (int m = 0; m < 2; ++m) {
        const int t = pp + 32 * m;
#pragma unroll
        for (int x = 0; x < 8; ++x) buf[x] = V[t * 16 + c + x * 1024];
        fft8p<1>(buf);
#pragma unroll
        for (int x = 0; x < 8; ++x) {
            float re, im;
            upk(buf[x], re, im);
            og[(long)(x * 64 + t) * 32] =
                make_float2(re * (1.f / 512.f) + bv.x, im * (1.f / 512.f) + bv.y);
        }
    }
}

// ---------------------------------------------------------------------------
// Launch: fwd normal; pointwise + ifft with the PDL attribute.
// ---------------------------------------------------------------------------
extern "C" void kernel_launch(void* const* d_in, const int* in_sizes, int n_in,
                              void* d_out, int out_size) {
    const float* inputs = (const float*)d_in[0];
    const float* kern   = (const float*)d_in[1];
    const float* bias   = (const float*)d_in[2];
    float* out = (float*)d_out;

    ull *Xp, *Wp, *Zh;
    cudaGetSymbolAddress((void**)&Xp, g_Xp);
    cudaGetSymbolAddress((void**)&Wp, g_Wp);
    cudaGetSymbolAddress((void**)&Zh, g_Z);

    const int smemFFT = 512 * 16 * (int)sizeof(ull);       // 65536 B
    const int smemPW  = 2 * 64 * 65 * (int)sizeof(float2); // 66560 B
    cudaFuncSetAttribute(fft3d_fwd_packed, cudaFuncAttributeMaxDynamicSharedMemorySize, smemFFT);
    cudaFuncSetAttribute(ifft3d_packed,    cudaFuncAttributeMaxDynamicSharedMemorySize, smemFFT);
    cudaFuncSetAttribute(pointwise_kernel, cudaFuncAttributeMaxDynamicSharedMemorySize, smemPW);

    fft3d_fwd_packed<<<256, 512, smemFFT>>>(inputs, kern, Xp, Wp);

    cudaLaunchAttribute attrs[1];
    attrs[0].id = cudaLaunchAttributeProgrammaticStreamSerialization;
    attrs[0].val.programmaticStreamSerializationAllowed = 1;

    {
        cudaLaunchConfig_t cfg = {};
        cfg.gridDim = dim3(260, 1, 1);
        cfg.blockDim = dim3(256, 1, 1);
        cfg.dynamicSmemBytes = smemPW;
        cfg.attrs = attrs;
        cfg.numAttrs = 1;
        cudaLaunchKernelEx(&cfg, pointwise_kernel,
                           (const float2*)Xp, (const float2*)Wp, (float2*)Zh);
    }
    {
        cudaLaunchConfig_t cfg = {};
        cfg.gridDim = dim3(128, 1, 1);
        cfg.blockDim = dim3(512, 1, 1);
        cfg.dynamicSmemBytes = smemFFT;
        cfg.attrs = attrs;
        cfg.numAttrs = 1;
        cudaLaunchKernelEx(&cfg, ifft3d_packed, (const ull*)Zh, bias, out);
    }
}

// round 10
// speedup vs baseline: 1.2944x; 1.2944x over previous
#include <cuda_runtime.h>

// ============================================================================
// TorusConv3D via FFT diagonalization (round 10).
// Round-10: ONE persistent kernel (grid 260 x 512 threads, fully wave-1
// resident) with two software grid barriers replacing the two inter-kernel
// launch/drain gaps (~8-10us of the round-8 wall time). PDL from round 9
// reverted (dependent CTAs stole residency). Stage bodies = per-stage
// measured winners (packed f32x2 butterflies; Hermitian pointwise GEMM).
// ============================================================================

typedef unsigned long long ull;

// Packed spectra: g_Xp[k*2048 + b*32 + j], g_Wp[k*2048 + f*32 + j],
//                 g_Z [k*2048 + b*32 + fp]
__device__ ull g_Xp[512 * 2048];
__device__ ull g_Wp[512 * 2048];
__device__ ull g_Z[512 * 2048];

// Software grid barrier state (count resets each use; gen is monotonic across
// graph replays, so no cross-launch reset is needed).
__device__ unsigned g_cnt[2];
__device__ unsigned g_gen[2];

#define GRID_CTAS 260

__device__ __forceinline__ void grid_barrier(int which) {
    __syncthreads();
    if (threadIdx.x == 0) {
        const unsigned my = atomicAdd(&g_gen[which], 0u);  // read gen BEFORE arriving
        __threadfence();                                    // release my stage's writes
        const unsigned old = atomicAdd(&g_cnt[which], 1u);
        if (old == GRID_CTAS - 1) {
            g_cnt[which] = 0;      // reset for next replay/use
            __threadfence();
            atomicAdd(&g_gen[which], 1u);  // release
        } else {
            while (atomicAdd(&g_gen[which], 0u) == my) { }  // acquire spin
        }
    }
    __syncthreads();
}

// ---------------------------------------------------------------------------
// Packed f32x2 primitives. A complex value is (re, im) = (lo, hi) of an ull.
// ---------------------------------------------------------------------------
__device__ __forceinline__ ull pk(float lo, float hi) {
    ull r;
    asm("mov.b64 %0, {%1, %2};" : "=l"(r) : "f"(lo), "f"(hi));
    return r;
}
__device__ __forceinline__ void upk(ull v, float& lo, float& hi) {
    asm("mov.b64 {%0, %1}, %2;" : "=f"(lo), "=f"(hi) : "l"(v));
}
__device__ __forceinline__ ull add2(ull a, ull b) {
    ull d;
    asm("add.rn.f32x2 %0, %1, %2;" : "=l"(d) : "l"(a), "l"(b));
    return d;
}
__device__ __forceinline__ ull mul2(ull a, ull b) {
    ull d;
    asm("mul.rn.f32x2 %0, %1, %2;" : "=l"(d) : "l"(a), "l"(b));
    return d;
}
__device__ __forceinline__ ull fma2(ull a, ull b, ull c) {
    ull d;
    asm("fma.rn.f32x2 %0, %1, %2, %3;" : "=l"(d) : "l"(a), "l"(b), "l"(c));
    return d;
}
__device__ __forceinline__ ull sub2(ull a, ull b) {
    return fma2(b, 0xBF800000BF800000ULL, a);  // a + (-1)*b
}
__device__ __forceinline__ float negf(float x) {
    return __uint_as_float(__float_as_uint(x) ^ 0x80000000u);
}
template <int INV>
__device__ __forceinline__ ull mi(ull a) {  // *(-i) fwd, *(+i) inv
    float x, y;
    upk(a, x, y);
    return INV ? pk(negf(y), x) : pk(y, negf(x));
}

#define R2R2 0x3F3504F33F3504F3ULL  // (sqrt(0.5), sqrt(0.5))

template <int INV>
__device__ __forceinline__ void fft8p(ull* v) {
    ull t0 = add2(v[0], v[4]), t1 = sub2(v[0], v[4]);
    ull t2 = add2(v[2], v[6]), t3 = sub2(v[2], v[6]);
    ull t4 = add2(v[1], v[5]), t5 = sub2(v[1], v[5]);
    ull t6 = add2(v[3], v[7]), t7 = sub2(v[3], v[7]);
    ull a0 = add2(t0, t2), a1 = sub2(t0, t2);
    ull m3 = mi<INV>(t3);
    ull a2 = add2(t1, m3), a3 = sub2(t1, m3);
    ull b0 = add2(t4, t6), b1 = sub2(t4, t6);
    ull m7 = mi<INV>(t7);
    ull b2 = add2(t5, m7), b3 = sub2(t5, m7);
    ull mb1 = mi<INV>(b1);
    ull w1v = mul2(add2(b2, mi<INV>(b2)), R2R2);
    ull w3v = mi<INV>(mul2(add2(b3, mi<INV>(b3)), R2R2));
    v[0] = add2(a0, b0); v[4] = sub2(a0, b0);
    v[2] = add2(a1, mb1); v[6] = sub2(a1, mb1);
    v[1] = add2(a2, w1v); v[5] = sub2(a2, w1v);
    v[3] = add2(a3, w3v); v[7] = sub2(a3, w3v);
}

// ---------------------------------------------------------------------------
// The fused persistent kernel. smem is a union:
//   FFT stages:  ull  V[512*16]            (64 KB)
//   pointwise:   float2 As[64*65] + Bs[64*65]  (66.56 KB)
// ---------------------------------------------------------------------------
__global__ void __launch_bounds__(512, 2)
torus_fused(const float* __restrict__ inputs, const float* __restrict__ kern,
            const float* __restrict__ bias, float* __restrict__ out) {
    extern __shared__ ull SM[];
    const int blk = blockIdx.x;
    const int tid = threadIdx.x;

    // ======================= Stage A: forward FFT =======================
    // 256 tasks: blk<128 -> inputs->Xp, 128..255 -> kernel->Wp. 4 CTAs idle.
    if (blk < 256) {
        ull* V = SM;
        int t_ = blk;
        const float* in;
        ull* outp;
        long rowStride, sStride;
        if (t_ < 128) { in = inputs; outp = g_Xp; rowStride = 32768; sStride = 64; }
        else          { t_ -= 128; in = kern; outp = g_Wp; rowStride = 64; sStride = 4096; }
        const int row = t_ >> 1, j0 = (t_ & 1) * 16;
        const int c = tid & 15, pp = tid >> 4;

        const float* base = in + (long)row * rowStride + 2 * (j0 + c);
        ull buf[8];

#pragma unroll
        for (int m = 0; m < 2; ++m) {  // z-axis + load
            const int t = pp + 32 * m;
#pragma unroll
            for (int z = 0; z < 8; ++z)
                buf[z] = *(const ull*)(base + (long)(8 * t + z) * sStride);
            fft8p<0>(buf);
#pragma unroll
            for (int z = 0; z < 8; ++z) V[(8 * t + z) * 16 + c] = buf[z];
        }
        __syncthreads();
#pragma unroll
        for (int m = 0; m < 2; ++m) {  // y-axis
            const int t = pp + 32 * m;
            const int b0 = ((t >> 3) * 64 + (t & 7)) * 16 + c;
#pragma unroll
            for (int y = 0; y < 8; ++y) buf[y] = V[b0 + y * 128];
            fft8p<0>(buf);
#pragma unroll
            for (int y = 0; y < 8; ++y) V[b0 + y * 128] = buf[y];
        }
        __syncthreads();
        ull* og = outp + row * 32 + j0 + c;
#pragma unroll
        for (int m = 0; m < 2; ++m) {  // x-axis + store
            const int t = pp + 32 * m;
#pragma unroll
            for (int x = 0; x < 8; ++x) buf[x] = V[t * 16 + c + x * 1024];
            fft8p<0>(buf);
#pragma unroll
            for (int x = 0; x < 8; ++x) og[(long)(x * 64 + t) * 2048] = buf[x];
        }
    }

    grid_barrier(0);

    // ======================= Stage B: pointwise GEMM =======================
    // 260 tasks, 1:1 with CTAs. 512 threads, 2x4 tiles.
    {
        float2* As = (float2*)SM;       // [c][b], stride 65
        float2* Bs = (float2*)SM + 64 * 65;  // [c][f], stride 65
        const int rank = blk;
        int kx, ky, kz;
        if (rank < 192) {
            kx = 1 + rank / 64; const int r = rank & 63; ky = r >> 3; kz = r & 7;
        } else if (rank < 240) {
            const int r = rank - 192; kx = (r / 24) * 4;
            const int r2 = r % 24; ky = 1 + r2 / 8; kz = r2 & 7;
        } else {
            const int r = rank - 240; kx = (r / 10) * 4;
            const int r2 = r % 10; ky = (r2 / 5) * 4; kz = r2 % 5;
        }
        const int k = (kx << 6) | (ky << 3) | kz;
        const int neg = (((8 - kx) & 7) << 6) | (((8 - ky) & 7) << 3) | ((8 - kz) & 7);

        const float2* xk = (const float2*)g_Xp + (long)k * 2048;
        const float2* xn = (const float2*)g_Xp + (long)neg * 2048;
        const float2* wk = (const float2*)g_Wp + (long)k * 2048;
        const float2* wn = (const float2*)g_Wp + (long)neg * 2048;
        for (int i = tid; i < 2048; i += 512) {
            const int j = i & 31, rowi = i >> 5;
            const int c0 = 2 * j, c1 = 2 * j + 1;
            {
                const float2 Pk = xk[i], Pn = xn[i];
                As[c0 * 65 + rowi] = make_float2(0.5f * (Pk.x + Pn.x), 0.5f * (Pk.y - Pn.y));
                As[c1 * 65 + rowi] = make_float2(0.5f * (Pk.y + Pn.y), 0.5f * (Pn.x - Pk.x));
            }
            {
                const float2 Pk = wk[i], Pn = wn[i];
                Bs[c0 * 65 + rowi] = make_float2(0.5f * (Pk.x + Pn.x), 0.5f * (Pk.y - Pn.y));
                Bs[c1 * 65 + rowi] = make_float2(0.5f * (Pk.y + Pn.y), 0.5f * (Pn.x - Pk.x));
            }
        }
        __syncthreads();

        const int ft = tid & 15;   // f = ft + 16j
        const int bt = tid >> 4;   // b = bt + 32i, bt in 0..31
        ull acc[2][4];
#pragma unroll
        for (int i = 0; i < 2; ++i)
#pragma unroll
            for (int j = 0; j < 4; ++j) acc[i][j] = 0ULL;

        ull axax[2], nay[2], bxy[4], byx[4];
#pragma unroll 2
        for (int cc = 0; cc < 64; ++cc) {
#pragma unroll
            for (int i = 0; i < 2; ++i) {
                const float2 t = As[cc * 65 + bt + 32 * i];
                axax[i] = pk(t.x, t.x);
                nay[i] = pk(negf(t.y), t.y);
            }
#pragma unroll
            for (int j = 0; j < 4; ++j) {
                const float2 t = Bs[cc * 65 + ft + 16 * j];
                bxy[j] = pk(t.x, t.y);
                byx[j] = pk(t.y, t.x);
            }
#pragma unroll
            for (int i = 0; i < 2; ++i)
#pragma unroll
                for (int j = 0; j < 4; ++j) {
                    acc[i][j] = fma2(axax[i], bxy[j], acc[i][j]);
                    acc[i][j] = fma2(nay[i], byx[j], acc[i][j]);
                }
        }

        float2* zk = (float2*)g_Z + (long)k * 2048;
        float2* zn = (float2*)g_Z + (long)neg * 2048;
        const bool self = (k == neg);
        const bool even = (ft & 1) == 0;
        const int fp0 = ft >> 1;
#pragma unroll
        for (int i = 0; i < 2; ++i)
#pragma unroll
            for (int j = 0; j < 4; ++j) {
                const ull part = __shfl_xor_sync(0xffffffffu, acc[i][j], 1);
                if (even) {
                    float y0x, y0y, y1x, y1y;
                    upk(acc[i][j], y0x, y0y);
                    upk(part, y1x, y1y);
                    const int idx = (bt + 32 * i) * 32 + fp0 + 8 * j;
                    zk[idx] = make_float2(y0x - y1y, y0y + y1x);
                    if (!self) zn[idx] = make_float2(y0x + y1y, y1x - y0y);
                }
            }
    }

    grid_barrier(1);

    // ======================= Stage C: inverse FFT =======================
    // 128 tasks: blk < 128, b = blk>>1, fp half. 512 threads.
    if (blk < 128) {
        ull* V = SM;
        const int b = blk >> 1, fp0 = (blk & 1) * 16;
        const int c = tid & 15, pp = tid >> 4;
        const float2 bv = ((const float2*)bias)[fp0 + c];

        const ull* yg = g_Z + b * 32 + fp0 + c;
        ull buf[8];

#pragma unroll
        for (int m = 0; m < 2; ++m) {  // z-axis + load
            const int t = pp + 32 * m;
#pragma unroll
            for (int z = 0; z < 8; ++z) buf[z] = yg[(long)(8 * t + z) * 2048];
            fft8p<1>(buf);
#pragma unroll
            for (int z = 0; z < 8; ++z) V[(8 * t + z) * 16 + c] = buf[z];
        }
        __syncthreads();
#pragma unroll
        for (int m = 0; m < 2; ++m) {  // y-axis
            const int t = pp + 32 * m;
            const int b0 = ((t >> 3) * 64 + (t & 7)) * 16 + c;
#pragma unroll
            for (int y = 0; y < 8; ++y) buf[y] = V[b0 + y * 128];
            fft8p<1>(buf);
#pragma unroll
            for (int y = 0; y < 8; ++y) V[b0 + y * 128] = buf[y];
        }
        __syncthreads();
        float2* og = (float2*)out + (long)b * 512 * 32 + fp0 + c;
#pragma unroll
        for (int m = 0; m < 2; ++m) {  // x-axis + store
            const int t = pp + 32 * m;
#pragma unroll
            for (int x = 0; x < 8; ++x) buf[x] = V[t * 16 + c + x * 1024];
            fft8p<1>(buf);
#pragma unroll
            for (int x = 0; x < 8; ++x) {
                float re, im;
                upk(buf[x], re, im);
                og[(long)(x * 64 + t) * 32] =
                    make_float2(re * (1.f / 512.f) + bv.x, im * (1.f / 512.f) + bv.y);
            }
        }
    }
}

// ---------------------------------------------------------------------------
extern "C" void kernel_launch(void* const* d_in, const int* in_sizes, int n_in,
                              void* d_out, int out_size) {
    const float* inputs = (const float*)d_in[0];
    const float* kern   = (const float*)d_in[1];
    const float* bias   = (const float*)d_in[2];
    float* out = (float*)d_out;

    const int smemBytes = 2 * 64 * 65 * (int)sizeof(float2);  // 66560 B (>= 64KB FFT)
    cudaFuncSetAttribute(torus_fused, cudaFuncAttributeMaxDynamicSharedMemorySize, smemBytes);

    torus_fused<<<GRID_CTAS, 512, smemBytes>>>(inputs, kern, bias, out);
}